// round 2
// baseline (speedup 1.0000x reference)
#include <cuda_runtime.h>
#include <cstdint>

#define DIMC 768
#define HEADS 12
#define NTOK 64
#define DH 64

// ---------------- scratch (device globals; no allocation allowed) ----------------
__device__ float g_q[65536 * 768];
__device__ float g_k[65536 * 768];
__device__ float g_v[65536 * 768];
__device__ float g_c[65536 * 768];
__device__ float g_tbl[343 * 12];
__device__ float g_bias[12 * 64 * 64];

// ---------------- helpers ----------------
__device__ __forceinline__ void cp_async16(void* s, const void* g) {
    uint32_t sa = (uint32_t)__cvta_generic_to_shared(s);
    asm volatile("cp.async.cg.shared.global [%0], [%1], 16;\n" ::"r"(sa), "l"(g) : "memory");
}
__device__ __forceinline__ void cp_commit() { asm volatile("cp.async.commit_group;\n" ::: "memory"); }
__device__ __forceinline__ void cp_wait0() { asm volatile("cp.async.wait_group 0;\n" ::: "memory"); }

__device__ __forceinline__ uint32_t f2tf32(float f) {
    uint32_t r;
    asm("cvt.rna.tf32.f32 %0, %1;" : "=r"(r) : "f"(f));
    return r;
}

__device__ __forceinline__ void mma_tf32(float* c, const uint32_t* a, const uint32_t* b) {
    asm volatile(
        "mma.sync.aligned.m16n8k8.row.col.f32.tf32.tf32.f32 "
        "{%0,%1,%2,%3},{%4,%5,%6,%7},{%8,%9},{%0,%1,%2,%3};"
        : "+f"(c[0]), "+f"(c[1]), "+f"(c[2]), "+f"(c[3])
        : "r"(a[0]), "r"(a[1]), "r"(a[2]), "r"(a[3]), "r"(b[0]), "r"(b[1]));
}

// ---------------- TF32 GEMM: C[M,768] = A[M,768] @ B[768,768] (+bias) ----------------
// CTA tile 128x128, K tile 32, 8 warps (2x4), warp tile 64x32, double-buffered cp.async.
#define TILE_M 128
#define TILE_N 128
#define TILE_K 32
#define AS_STRIDE 36   // (m*4+k)%32 unique -> conflict free frag loads
#define BS_STRIDE 136  // (k*8+n)%32 unique -> conflict free frag loads
#define GEMM_SMEM ((2 * TILE_M * AS_STRIDE + 2 * TILE_K * BS_STRIDE) * 4)

__global__ void __launch_bounds__(256) gemm_tf32_kernel(
    const float* __restrict__ A, const float* __restrict__ B,
    const float* __restrict__ bias, float* __restrict__ C) {
    extern __shared__ float smem[];
    float* As = smem;                            // 2 x 128*36
    float* Bs = smem + 2 * TILE_M * AS_STRIDE;   // 2 x 32*136

    const int tid = threadIdx.x;
    const int bm = blockIdx.y, bn = blockIdx.x;
    const int lane = tid & 31, warp = tid >> 5;
    const int wm = (warp & 1) * 64, wn = (warp >> 1) * 32;

    // load mapping
    const int ar = tid >> 3;          // 0..31 (row within a 32-row pass)
    const int ac = (tid & 7) * 4;     // col (floats)
    const int br = tid >> 5;          // 0..7
    const int bc = (tid & 31) * 4;    // 0..124

    const float* Ag = A + (size_t)(bm * TILE_M) * DIMC;
    const float* Bg = B + bn * TILE_N;

    float acc[4][4][4];
#pragma unroll
    for (int i = 0; i < 4; i++)
#pragma unroll
        for (int j = 0; j < 4; j++)
#pragma unroll
            for (int k = 0; k < 4; k++) acc[i][j][k] = 0.f;

    const int NK = DIMC / TILE_K;  // 24

    // stage loader
    auto load_stage = [&](int kt, int s) {
        float* as = As + s * TILE_M * AS_STRIDE;
        float* bs = Bs + s * TILE_K * BS_STRIDE;
        const float* ag = Ag + kt * TILE_K;
#pragma unroll
        for (int p = 0; p < 4; p++) {
            int r = p * 32 + ar;
            cp_async16(as + r * AS_STRIDE + ac, ag + (size_t)r * DIMC + ac);
        }
        const float* bg = Bg + (size_t)(kt * TILE_K) * DIMC;
#pragma unroll
        for (int p = 0; p < 4; p++) {
            int r = p * 8 + br;
            cp_async16(bs + r * BS_STRIDE + bc, bg + (size_t)r * DIMC + bc);
        }
        cp_commit();
    };

    load_stage(0, 0);

    for (int kt = 0; kt < NK; kt++) {
        const int s = kt & 1;
        cp_wait0();
        __syncthreads();
        if (kt + 1 < NK) load_stage(kt + 1, s ^ 1);

        const float* as = As + s * TILE_M * AS_STRIDE;
        const float* bs = Bs + s * TILE_K * BS_STRIDE;
#pragma unroll
        for (int ks = 0; ks < 4; ks++) {
            const int k0 = ks * 8;
            uint32_t af[4][4], bf[4][2];
#pragma unroll
            for (int mt = 0; mt < 4; mt++) {
                const int rb = wm + mt * 16 + (lane >> 2);
                const int cc = k0 + (lane & 3);
                af[mt][0] = f2tf32(as[rb * AS_STRIDE + cc]);
                af[mt][1] = f2tf32(as[(rb + 8) * AS_STRIDE + cc]);
                af[mt][2] = f2tf32(as[rb * AS_STRIDE + cc + 4]);
                af[mt][3] = f2tf32(as[(rb + 8) * AS_STRIDE + cc + 4]);
            }
#pragma unroll
            for (int nt = 0; nt < 4; nt++) {
                const int cb = wn + nt * 8 + (lane >> 2);
                const int rr = k0 + (lane & 3);
                bf[nt][0] = f2tf32(bs[rr * BS_STRIDE + cb]);
                bf[nt][1] = f2tf32(bs[(rr + 4) * BS_STRIDE + cb]);
            }
#pragma unroll
            for (int mt = 0; mt < 4; mt++)
#pragma unroll
                for (int nt = 0; nt < 4; nt++) mma_tf32(acc[mt][nt], af[mt], bf[nt]);
        }
        __syncthreads();
    }

    // epilogue
#pragma unroll
    for (int mt = 0; mt < 4; mt++) {
#pragma unroll
        for (int nt = 0; nt < 4; nt++) {
            const int row = bm * TILE_M + wm + mt * 16 + (lane >> 2);
            const int col = bn * TILE_N + wn + nt * 8 + (lane & 3) * 2;
            const float b0 = bias ? bias[col] : 0.f;
            const float b1 = bias ? bias[col + 1] : 0.f;
            float2 v0 = make_float2(acc[mt][nt][0] + b0, acc[mt][nt][1] + b1);
            float2 v1 = make_float2(acc[mt][nt][2] + b0, acc[mt][nt][3] + b1);
            *(float2*)&C[(size_t)row * DIMC + col] = v0;
            *(float2*)&C[(size_t)(row + 8) * DIMC + col] = v1;
        }
    }
}

// ---------------- CPB MLP -> table (343 x 12) ----------------
__global__ void cpb_kernel(const float* __restrict__ tabl, const float* __restrict__ w1,
                           const float* __restrict__ b1, const float* __restrict__ w2,
                           const float* __restrict__ b2) {
    __shared__ float red[128 * 12];
    const int r = blockIdx.x;
    const int t = threadIdx.x;
    const float t0 = tabl[r * 3 + 0], t1 = tabl[r * 3 + 1], t2 = tabl[r * 3 + 2];
    float part[12];
#pragma unroll
    for (int hh = 0; hh < 12; hh++) part[hh] = 0.f;
    for (int j = t; j < 512; j += 128) {
        float h = t0 * w1[j] + t1 * w1[512 + j] + t2 * w1[1024 + j] + b1[j];
        h = fmaxf(h, 0.f);
#pragma unroll
        for (int hh = 0; hh < 12; hh++) part[hh] += h * w2[j * 12 + hh];
    }
#pragma unroll
    for (int hh = 0; hh < 12; hh++) red[t * 12 + hh] = part[hh];
    __syncthreads();
    if (t < 12) {
        float s = b2[t];
        for (int i = 0; i < 128; i++) s += red[i * 12 + t];
        g_tbl[r * 12 + t] = s;
    }
}

// ---------------- gather + 16*sigmoid -> g_bias[h][i*64+j] ----------------
__global__ void bias_kernel(const int* __restrict__ idx) {
    const int g = blockIdx.x * blockDim.x + threadIdx.x;
    if (g >= 12 * 4096) return;
    const int h = g / 4096, ij = g % 4096;
    const float x = g_tbl[idx[ij] * 12 + h];
    g_bias[g] = 16.f / (1.f + __expf(-x));
}

// ---------------- fused attention per (window, head) ----------------
// smem: qs[64*65] kT[64*65] vs[64*64] ps[64*65] qn[64] kn[64]
#define ATTN_SMEM ((64 * 65 * 3 + 64 * 64 + 128) * 4)

__global__ void __launch_bounds__(128) attn_kernel(
    const float* __restrict__ Q, const float* __restrict__ K,
    const float* __restrict__ V, const float* __restrict__ LS,
    float* __restrict__ O) {
    extern __shared__ float sm[];
    float* qs = sm;                 // [i*65+d]
    float* kT = qs + 64 * 65;       // [d*65+j]
    float* vs = kT + 64 * 65;       // [j*64+d]
    float* ps = vs + 64 * 64;       // [i*65+j]
    float* qn = ps + 64 * 65;
    float* kn = qn + 64;

    const int b = blockIdx.x, h = blockIdx.y;
    const int t = threadIdx.x;
    const size_t base = ((size_t)b * NTOK) * DIMC + h * DH;

    for (int idx = t; idx < 4096; idx += 128) {
        const int r = idx >> 6, d = idx & 63;
        const size_t off = base + (size_t)r * DIMC + d;
        qs[r * 65 + d] = Q[off];
        kT[d * 65 + r] = K[off];
        vs[r * 64 + d] = V[off];
    }
    __syncthreads();

    if (t < 64) {
        float s = 0.f;
#pragma unroll 8
        for (int d = 0; d < 64; d++) { float x = qs[t * 65 + d]; s += x * x; }
        qn[t] = sqrtf(s);
    } else {
        const int j = t - 64;
        float s = 0.f;
#pragma unroll 8
        for (int d = 0; d < 64; d++) { float x = kT[d * 65 + j]; s += x * x; }
        kn[j] = sqrtf(s);
    }
    __syncthreads();

    const float scale = fmaxf(LS[h], 0.01f);
    const float* bg = g_bias + h * 4096;

    // S = q@k^T / denom * scale + bias16 ; each thread computes a 4x8 tile
    {
        const int ti = t >> 3, tj = t & 7;
        const int i0 = ti * 4, j0 = tj * 8;
        float acc[4][8];
#pragma unroll
        for (int ii = 0; ii < 4; ii++)
#pragma unroll
            for (int jj = 0; jj < 8; jj++) acc[ii][jj] = 0.f;
#pragma unroll 4
        for (int d = 0; d < 64; d++) {
            float qv[4], kv[8];
#pragma unroll
            for (int ii = 0; ii < 4; ii++) qv[ii] = qs[(i0 + ii) * 65 + d];
#pragma unroll
            for (int jj = 0; jj < 8; jj++) kv[jj] = kT[d * 65 + j0 + jj];
#pragma unroll
            for (int ii = 0; ii < 4; ii++)
#pragma unroll
                for (int jj = 0; jj < 8; jj++) acc[ii][jj] += qv[ii] * kv[jj];
        }
#pragma unroll
        for (int ii = 0; ii < 4; ii++)
#pragma unroll
            for (int jj = 0; jj < 8; jj++) {
                const int i = i0 + ii, j = j0 + jj;
                const float den = fmaxf(qn[i] * kn[j], 1e-6f);
                ps[i * 65 + j] = acc[ii][jj] / den * scale + bg[i * 64 + j];
            }
    }
    __syncthreads();

    // softmax rows
    if (t < 64) {
        float m = -1e30f;
#pragma unroll 8
        for (int j = 0; j < 64; j++) m = fmaxf(m, ps[t * 65 + j]);
        float s = 0.f;
#pragma unroll 8
        for (int j = 0; j < 64; j++) {
            const float e = __expf(ps[t * 65 + j] - m);
            ps[t * 65 + j] = e;
            s += e;
        }
        const float inv = 1.f / s;
#pragma unroll 8
        for (int j = 0; j < 64; j++) ps[t * 65 + j] *= inv;
    }
    __syncthreads();

    // O = P @ V ; 4x8 tile per thread over (i, d)
    {
        const int ti = t >> 3, tj = t & 7;
        const int i0 = ti * 4, d0 = tj * 8;
        float acc[4][8];
#pragma unroll
        for (int ii = 0; ii < 4; ii++)
#pragma unroll
            for (int dd = 0; dd < 8; dd++) acc[ii][dd] = 0.f;
#pragma unroll 4
        for (int j = 0; j < 64; j++) {
            float pv[4], vv[8];
#pragma unroll
            for (int ii = 0; ii < 4; ii++) pv[ii] = ps[(i0 + ii) * 65 + j];
#pragma unroll
            for (int dd = 0; dd < 8; dd++) vv[dd] = vs[j * 64 + d0 + dd];
#pragma unroll
            for (int ii = 0; ii < 4; ii++)
#pragma unroll
                for (int dd = 0; dd < 8; dd++) acc[ii][dd] += pv[ii] * vv[dd];
        }
#pragma unroll
        for (int ii = 0; ii < 4; ii++)
#pragma unroll
            for (int dd = 0; dd < 8; dd++)
                O[base + (size_t)(i0 + ii) * DIMC + d0 + dd] = acc[ii][dd];
    }
}

// ---------------- launch ----------------
extern "C" void kernel_launch(void* const* d_in, const int* in_sizes, int n_in,
                              void* d_out, int out_size) {
    const float* x   = (const float*)d_in[0];
    const float* q_w = (const float*)d_in[1];
    const float* q_b = (const float*)d_in[2];
    const float* k_w = (const float*)d_in[3];
    const float* v_w = (const float*)d_in[4];
    const float* v_b = (const float*)d_in[5];
    const float* cw1 = (const float*)d_in[6];
    const float* cb1 = (const float*)d_in[7];
    const float* cw2 = (const float*)d_in[8];
    const float* cb2 = (const float*)d_in[9];
    const float* ls  = (const float*)d_in[10];
    const float* pw  = (const float*)d_in[11];
    const float* pb  = (const float*)d_in[12];
    const float* tab = (const float*)d_in[13];
    const int*   idx = (const int*)d_in[14];
    float* out = (float*)d_out;

    const int rows = in_sizes[0] / DIMC;  // 65536
    const int B = rows / NTOK;            // 1024

    float *dq, *dk, *dv, *dc;
    cudaGetSymbolAddress((void**)&dq, g_q);
    cudaGetSymbolAddress((void**)&dk, g_k);
    cudaGetSymbolAddress((void**)&dv, g_v);
    cudaGetSymbolAddress((void**)&dc, g_c);

    cudaFuncSetAttribute(gemm_tf32_kernel, cudaFuncAttributeMaxDynamicSharedMemorySize, GEMM_SMEM);
    cudaFuncSetAttribute(attn_kernel, cudaFuncAttributeMaxDynamicSharedMemorySize, ATTN_SMEM);

    cpb_kernel<<<343, 128>>>(tab, cw1, cb1, cw2, cb2);
    bias_kernel<<<(12 * 4096 + 255) / 256, 256>>>(idx);

    dim3 gg(DIMC / TILE_N, rows / TILE_M);
    gemm_tf32_kernel<<<gg, 256, GEMM_SMEM>>>(x, q_w, q_b, dq);
    gemm_tf32_kernel<<<gg, 256, GEMM_SMEM>>>(x, k_w, nullptr, dk);
    gemm_tf32_kernel<<<gg, 256, GEMM_SMEM>>>(x, v_w, v_b, dv);

    dim3 ga(B, HEADS);
    attn_kernel<<<ga, 128, ATTN_SMEM>>>(dq, dk, dv, ls, dc);

    gemm_tf32_kernel<<<gg, 256, GEMM_SMEM>>>(dc, pw, pb, out);
}

// round 4
// speedup vs baseline: 1.7308x; 1.7308x over previous
#include <cuda_runtime.h>
#include <cuda_fp16.h>
#include <cstdint>

#define DIMC 768
#define HEADS 12
#define NTOK 64
#define DH 64

// ---------------- scratch (device globals) ----------------
__device__ float g_q[65536 * 768];
__device__ float g_k[65536 * 768];
__device__ float g_v[65536 * 768];
__device__ __half g_xh[65536 * 768];   // x in fp16
__device__ __half g_ch[65536 * 768];   // ctx in fp16
__device__ __half g_wh[2304 * 768];    // qkv weights transposed [n][k] fp16
__device__ __half g_wph[768 * 768];    // proj weight transposed fp16
__device__ float g_cbias[2304];
__device__ float g_tbl[343 * 12];
__device__ float g_bias[12 * 64 * 64];

// ---------------- helpers ----------------
__device__ __forceinline__ uint32_t smem_u32(const void* p) {
    uint32_t a;
    asm("{ .reg .u64 t; cvta.to.shared.u64 t, %1; cvt.u32.u64 %0, t; }" : "=r"(a) : "l"(p));
    return a;
}
__device__ __forceinline__ void cp16(uint32_t s, const void* g) {
    asm volatile("cp.async.cg.shared.global [%0], [%1], 16;" ::"r"(s), "l"(g) : "memory");
}
__device__ __forceinline__ void cp_commit() { asm volatile("cp.async.commit_group;" ::: "memory"); }
__device__ __forceinline__ void cp_wait1() { asm volatile("cp.async.wait_group 1;" ::: "memory"); }

__device__ __forceinline__ void ldsm4(uint32_t& r0, uint32_t& r1, uint32_t& r2, uint32_t& r3,
                                      uint32_t addr) {
    asm volatile("ldmatrix.sync.aligned.m8n8.x4.shared.b16 {%0,%1,%2,%3}, [%4];"
                 : "=r"(r0), "=r"(r1), "=r"(r2), "=r"(r3)
                 : "r"(addr));
}
__device__ __forceinline__ void mma_f16(float* c, const uint32_t* a, uint32_t b0, uint32_t b1) {
    asm volatile(
        "mma.sync.aligned.m16n8k16.row.col.f32.f16.f16.f32 "
        "{%0,%1,%2,%3},{%4,%5,%6,%7},{%8,%9},{%0,%1,%2,%3};"
        : "+f"(c[0]), "+f"(c[1]), "+f"(c[2]), "+f"(c[3])
        : "r"(a[0]), "r"(a[1]), "r"(a[2]), "r"(a[3]), "r"(b0), "r"(b1));
}

// ---------------- fp16 GEMM: C[M, Ncols] = A[M,768]fp16 @ Bt[Ncols,768]fp16 + bias ----------------
// CTA 128x128, BK=64 halves (128B rows), 3-stage cp.async pipeline, 8 warps (2x4), warp 64x32.
#define BK 64
#define STG_BYTES 32768          // A: 128*128B + B: 128*128B
#define NSTG 3
#define HG_SMEM (NSTG * STG_BYTES)
#define NKT (DIMC / BK)          // 12

__global__ void __launch_bounds__(256, 2) hgemm(
    const __half* __restrict__ A, const __half* __restrict__ Bt,
    const float* __restrict__ bias, float* __restrict__ out0,
    float* __restrict__ out1, float* __restrict__ out2) {
    extern __shared__ char smem[];
    const uint32_t sb = smem_u32(smem);
    const int tid = threadIdx.x;
    const int lane = tid & 31, warp = tid >> 5;
    const int bn = blockIdx.x, bm = blockIdx.y;
    const int wm = (warp & 1) * 64, wn = (warp >> 1) * 32;

    float acc[4][4][4];
#pragma unroll
    for (int i = 0; i < 4; i++)
#pragma unroll
        for (int j = 0; j < 4; j++)
#pragma unroll
            for (int k = 0; k < 4; k++) acc[i][j][k] = 0.f;

    const __half* Ab = A + (size_t)(bm * 128) * DIMC;
    const __half* Bb = Bt + (size_t)(bn * 128) * DIMC;

    auto load_stage = [&](int kt, int s) {
        const uint32_t st = sb + s * STG_BYTES;
#pragma unroll
        for (int i = 0; i < 8; i++) {
            const int c = tid + i * 256;
            if (c < 1024) {
                const int row = c >> 3, ch = c & 7;
                cp16(st + row * 128 + ((ch * 16) ^ ((row & 7) << 4)),
                     Ab + (size_t)row * DIMC + kt * BK + ch * 8);
            } else {
                const int cb = c - 1024;
                const int row = cb >> 3, ch = cb & 7;
                cp16(st + 16384 + row * 128 + ((ch * 16) ^ ((row & 7) << 4)),
                     Bb + (size_t)row * DIMC + kt * BK + ch * 8);
            }
        }
        cp_commit();
    };

    load_stage(0, 0);
    load_stage(1, 1);

    for (int kt = 0; kt < NKT; kt++) {
        cp_wait1();
        __syncthreads();
        if (kt + 2 < NKT) load_stage(kt + 2, (kt + 2) % NSTG);
        else cp_commit();

        const uint32_t sA = sb + (kt % NSTG) * STG_BYTES;
        const uint32_t sB = sA + 16384;
        const int l15 = lane & 15, lh = (lane >> 4) * 16;

#pragma unroll
        for (int ks = 0; ks < 4; ks++) {
            const int kb = ks * 32;
            uint32_t af[4][4], bf[2][4];
#pragma unroll
            for (int mt = 0; mt < 4; mt++) {
                const int row = wm + mt * 16 + l15;
                const uint32_t addr = sA + row * 128 + ((kb + lh) ^ ((row & 7) << 4));
                ldsm4(af[mt][0], af[mt][1], af[mt][2], af[mt][3], addr);
            }
#pragma unroll
            for (int bt = 0; bt < 2; bt++) {
                const int row = wn + bt * 16 + l15;
                const uint32_t addr = sB + row * 128 + ((kb + lh) ^ ((row & 7) << 4));
                ldsm4(bf[bt][0], bf[bt][1], bf[bt][2], bf[bt][3], addr);
            }
#pragma unroll
            for (int mt = 0; mt < 4; mt++) {
#pragma unroll
                for (int nt = 0; nt < 4; nt++) {
                    const int bt = nt >> 1, od = nt & 1;
                    mma_f16(acc[mt][nt], af[mt], bf[bt][od], bf[bt][od + 2]);
                }
            }
        }
        __syncthreads();
    }

    // epilogue: direct register -> global with bias
    const int matsel = (bn * 128) / DIMC;
    float* dst = matsel == 0 ? out0 : (matsel == 1 ? out1 : out2);
    const int lcbase = bn * 128 - matsel * DIMC;
#pragma unroll
    for (int mt = 0; mt < 4; mt++) {
#pragma unroll
        for (int nt = 0; nt < 4; nt++) {
            const int row = bm * 128 + wm + mt * 16 + (lane >> 2);
            const int tcol = wn + nt * 8 + (lane & 3) * 2;
            const int gc = bn * 128 + tcol;
            const float b0 = bias[gc], b1 = bias[gc + 1];
            const int lc = lcbase + tcol;
            float2 v0 = make_float2(acc[mt][nt][0] + b0, acc[mt][nt][1] + b1);
            float2 v1 = make_float2(acc[mt][nt][2] + b0, acc[mt][nt][3] + b1);
            *(float2*)&dst[(size_t)row * DIMC + lc] = v0;
            *(float2*)&dst[(size_t)(row + 8) * DIMC + lc] = v1;
        }
    }
}

// ---------------- pre-passes ----------------
__global__ void cvtx_kernel(const float4* __restrict__ in, uint2* __restrict__ out, int n4) {
    const int i = blockIdx.x * blockDim.x + threadIdx.x;
    if (i >= n4) return;
    const float4 v = in[i];
    __half2 h0 = __floats2half2_rn(v.x, v.y);
    __half2 h1 = __floats2half2_rn(v.z, v.w);
    out[i] = make_uint2(*(uint32_t*)&h0, *(uint32_t*)&h1);
}

// transpose fp32 [k][n] -> fp16 [n][k]
__global__ void trwh_kernel(const float* __restrict__ w, __half* __restrict__ dst) {
    __shared__ float t[32][33];
    const int bx = blockIdx.x * 32, by = blockIdx.y * 32;
    const int x = threadIdx.x, y = threadIdx.y;
#pragma unroll
    for (int i = 0; i < 32; i += 8) t[y + i][x] = w[(size_t)(by + y + i) * DIMC + bx + x];
    __syncthreads();
#pragma unroll
    for (int i = 0; i < 32; i += 8)
        dst[(size_t)(bx + y + i) * DIMC + by + x] = __float2half_rn(t[x][y + i]);
}

__global__ void cbias_kernel(const float* __restrict__ qb, const float* __restrict__ vb) {
    const int i = blockIdx.x * blockDim.x + threadIdx.x;
    if (i >= 2304) return;
    const int mat = i / DIMC, c = i - mat * DIMC;
    g_cbias[i] = mat == 0 ? qb[c] : (mat == 2 ? vb[c] : 0.f);
}

// ---------------- CPB MLP + bias gather ----------------
__global__ void cpb_kernel(const float* __restrict__ tabl, const float* __restrict__ w1,
                           const float* __restrict__ b1, const float* __restrict__ w2,
                           const float* __restrict__ b2) {
    __shared__ float red[128 * 12];
    const int r = blockIdx.x;
    const int t = threadIdx.x;
    const float t0 = tabl[r * 3 + 0], t1 = tabl[r * 3 + 1], t2 = tabl[r * 3 + 2];
    float part[12];
#pragma unroll
    for (int hh = 0; hh < 12; hh++) part[hh] = 0.f;
    for (int j = t; j < 512; j += 128) {
        float h = t0 * w1[j] + t1 * w1[512 + j] + t2 * w1[1024 + j] + b1[j];
        h = fmaxf(h, 0.f);
#pragma unroll
        for (int hh = 0; hh < 12; hh++) part[hh] += h * w2[j * 12 + hh];
    }
#pragma unroll
    for (int hh = 0; hh < 12; hh++) red[t * 12 + hh] = part[hh];
    __syncthreads();
    if (t < 12) {
        float s = b2[t];
        for (int i = 0; i < 128; i++) s += red[i * 12 + t];
        g_tbl[r * 12 + t] = s;
    }
}

__global__ void bias_kernel(const int* __restrict__ idx) {
    const int g = blockIdx.x * blockDim.x + threadIdx.x;
    if (g >= 12 * 4096) return;
    const int h = g / 4096, ij = g % 4096;
    const float x = g_tbl[idx[ij] * 12 + h];
    g_bias[g] = 16.f / (1.f + __expf(-x));
}

// ---------------- fused attention per (window, head) ----------------
#define ATTN_SMEM ((64 * 65 * 3 + 64 * 64 + 128) * 4)

__global__ void __launch_bounds__(128) attn_kernel(
    const float* __restrict__ Q, const float* __restrict__ K,
    const float* __restrict__ V, const float* __restrict__ LS,
    __half* __restrict__ O) {
    extern __shared__ float sm[];
    float* qs = sm;
    float* kT = qs + 64 * 65;
    float* vs = kT + 64 * 65;
    float* ps = vs + 64 * 64;
    float* qn = ps + 64 * 65;
    float* kn = qn + 64;

    const int b = blockIdx.x, h = blockIdx.y;
    const int t = threadIdx.x;
    const size_t base = ((size_t)b * NTOK) * DIMC + h * DH;

    for (int idx = t; idx < 4096; idx += 128) {
        const int r = idx >> 6, d = idx & 63;
        const size_t off = base + (size_t)r * DIMC + d;
        qs[r * 65 + d] = Q[off];
        kT[d * 65 + r] = K[off];
        vs[r * 64 + d] = V[off];
    }
    __syncthreads();

    if (t < 64) {
        float s = 0.f;
#pragma unroll 8
        for (int d = 0; d < 64; d++) { float x = qs[t * 65 + d]; s += x * x; }
        qn[t] = sqrtf(s);
    } else {
        const int j = t - 64;
        float s = 0.f;
#pragma unroll 8
        for (int d = 0; d < 64; d++) { float x = kT[d * 65 + j]; s += x * x; }
        kn[j] = sqrtf(s);
    }
    __syncthreads();

    const float scale = fmaxf(LS[h], 0.01f);
    const float* bg = g_bias + h * 4096;

    {
        const int ti = t >> 3, tj = t & 7;
        const int i0 = ti * 4, j0 = tj * 8;
        float acc[4][8];
#pragma unroll
        for (int ii = 0; ii < 4; ii++)
#pragma unroll
            for (int jj = 0; jj < 8; jj++) acc[ii][jj] = 0.f;
#pragma unroll 4
        for (int d = 0; d < 64; d++) {
            float qv[4], kv[8];
#pragma unroll
            for (int ii = 0; ii < 4; ii++) qv[ii] = qs[(i0 + ii) * 65 + d];
#pragma unroll
            for (int jj = 0; jj < 8; jj++) kv[jj] = kT[d * 65 + j0 + jj];
#pragma unroll
            for (int ii = 0; ii < 4; ii++)
#pragma unroll
                for (int jj = 0; jj < 8; jj++) acc[ii][jj] += qv[ii] * kv[jj];
        }
#pragma unroll
        for (int ii = 0; ii < 4; ii++)
#pragma unroll
            for (int jj = 0; jj < 8; jj++) {
                const int i = i0 + ii, j = j0 + jj;
                const float den = fmaxf(qn[i] * kn[j], 1e-6f);
                ps[i * 65 + j] = acc[ii][jj] / den * scale + bg[i * 64 + j];
            }
    }
    __syncthreads();

    if (t < 64) {
        float m = -1e30f;
#pragma unroll 8
        for (int j = 0; j < 64; j++) m = fmaxf(m, ps[t * 65 + j]);
        float s = 0.f;
#pragma unroll 8
        for (int j = 0; j < 64; j++) {
            const float e = __expf(ps[t * 65 + j] - m);
            ps[t * 65 + j] = e;
            s += e;
        }
        const float inv = 1.f / s;
#pragma unroll 8
        for (int j = 0; j < 64; j++) ps[t * 65 + j] *= inv;
    }
    __syncthreads();

    {
        const int ti = t >> 3, tj = t & 7;
        const int i0 = ti * 4, d0 = tj * 8;
        float acc[4][8];
#pragma unroll
        for (int ii = 0; ii < 4; ii++)
#pragma unroll
            for (int dd = 0; dd < 8; dd++) acc[ii][dd] = 0.f;
#pragma unroll 4
        for (int j = 0; j < 64; j++) {
            float pv[4], vv[8];
#pragma unroll
            for (int ii = 0; ii < 4; ii++) pv[ii] = ps[(i0 + ii) * 65 + j];
#pragma unroll
            for (int dd = 0; dd < 8; dd++) vv[dd] = vs[j * 64 + d0 + dd];
#pragma unroll
            for (int ii = 0; ii < 4; ii++)
#pragma unroll
                for (int dd = 0; dd < 8; dd++) acc[ii][dd] += pv[ii] * vv[dd];
        }
#pragma unroll
        for (int ii = 0; ii < 4; ii++)
#pragma unroll
            for (int dd = 0; dd < 8; dd++)
                O[base + (size_t)(i0 + ii) * DIMC + d0 + dd] = __float2half_rn(acc[ii][dd]);
    }
}

// ---------------- launch ----------------
extern "C" void kernel_launch(void* const* d_in, const int* in_sizes, int n_in,
                              void* d_out, int out_size) {
    const float* x   = (const float*)d_in[0];
    const float* q_w = (const float*)d_in[1];
    const float* q_b = (const float*)d_in[2];
    const float* k_w = (const float*)d_in[3];
    const float* v_w = (const float*)d_in[4];
    const float* v_b = (const float*)d_in[5];
    const float* cw1 = (const float*)d_in[6];
    const float* cb1 = (const float*)d_in[7];
    const float* cw2 = (const float*)d_in[8];
    const float* cb2 = (const float*)d_in[9];
    const float* ls  = (const float*)d_in[10];
    const float* pw  = (const float*)d_in[11];
    const float* pb  = (const float*)d_in[12];
    const float* tab = (const float*)d_in[13];
    const int*   idx = (const int*)d_in[14];
    float* out = (float*)d_out;

    const int rows = in_sizes[0] / DIMC;  // 65536
    const int B = rows / NTOK;            // 1024

    float *dq, *dk, *dv;
    __half *dxh, *dch, *dwh, *dwph;
    float* dcb;
    cudaGetSymbolAddress((void**)&dq, g_q);
    cudaGetSymbolAddress((void**)&dk, g_k);
    cudaGetSymbolAddress((void**)&dv, g_v);
    cudaGetSymbolAddress((void**)&dxh, g_xh);
    cudaGetSymbolAddress((void**)&dch, g_ch);
    cudaGetSymbolAddress((void**)&dwh, g_wh);
    cudaGetSymbolAddress((void**)&dwph, g_wph);
    cudaGetSymbolAddress((void**)&dcb, g_cbias);

    cudaFuncSetAttribute(hgemm, cudaFuncAttributeMaxDynamicSharedMemorySize, HG_SMEM);
    cudaFuncSetAttribute(attn_kernel, cudaFuncAttributeMaxDynamicSharedMemorySize, ATTN_SMEM);

    // pre-passes
    const int n4 = rows * DIMC / 4;
    cvtx_kernel<<<(n4 + 255) / 256, 256>>>((const float4*)x, (uint2*)dxh, n4);
    dim3 tb(32, 8), tg(24, 24);
    trwh_kernel<<<tg, tb>>>(q_w, dwh);
    trwh_kernel<<<tg, tb>>>(k_w, dwh + 768 * 768);
    trwh_kernel<<<tg, tb>>>(v_w, dwh + 2 * 768 * 768);
    trwh_kernel<<<tg, tb>>>(pw, dwph);
    cbias_kernel<<<9, 256>>>(q_b, v_b);
    cpb_kernel<<<343, 128>>>(tab, cw1, cb1, cw2, cb2);
    bias_kernel<<<(12 * 4096 + 255) / 256, 256>>>(idx);

    // fused QKV GEMM: [65536,768] x [768,2304] -> q,k,v (fp32)
    hgemm<<<dim3(2304 / 128, rows / 128), 256, HG_SMEM>>>(dxh, dwh, dcb, dq, dk, dv);

    // attention -> ctx (fp16)
    dim3 ga(B, HEADS);
    attn_kernel<<<ga, 128, ATTN_SMEM>>>(dq, dk, dv, ls, dch);

    // proj GEMM: [65536,768] x [768,768] -> out (fp32)
    hgemm<<<dim3(DIMC / 128, rows / 128), 256, HG_SMEM>>>(dch, dwph, pb, out, out, out);
}

// round 5
// speedup vs baseline: 2.5062x; 1.4480x over previous
#include <cuda_runtime.h>
#include <cuda_fp16.h>
#include <cstdint>

#define DIMC 768
#define HEADS 12
#define NTOK 64
#define DH 64

// ---------------- scratch (device globals) ----------------
__device__ __half g_qh[65536 * 768];
__device__ __half g_kh[65536 * 768];
__device__ __half g_vh[65536 * 768];
__device__ __half g_xh[65536 * 768];   // x in fp16
__device__ __half g_ch[65536 * 768];   // ctx in fp16
__device__ __half g_wh[2304 * 768];    // qkv weights transposed [n][k] fp16
__device__ __half g_wph[768 * 768];    // proj weight transposed fp16
__device__ float g_cbias[2304];
__device__ float g_tbl[343 * 12];
__device__ float g_bias[12 * 64 * 64];

// ---------------- helpers ----------------
__device__ __forceinline__ uint32_t smem_u32(const void* p) {
    uint32_t a;
    asm("{ .reg .u64 t; cvta.to.shared.u64 t, %1; cvt.u32.u64 %0, t; }" : "=r"(a) : "l"(p));
    return a;
}
__device__ __forceinline__ void cp16(uint32_t s, const void* g) {
    asm volatile("cp.async.cg.shared.global [%0], [%1], 16;" ::"r"(s), "l"(g) : "memory");
}
__device__ __forceinline__ void cp_commit() { asm volatile("cp.async.commit_group;" ::: "memory"); }
__device__ __forceinline__ void cp_wait1() { asm volatile("cp.async.wait_group 1;" ::: "memory"); }
__device__ __forceinline__ void cp_wait0() { asm volatile("cp.async.wait_group 0;" ::: "memory"); }

__device__ __forceinline__ void ldsm4(uint32_t& r0, uint32_t& r1, uint32_t& r2, uint32_t& r3,
                                      uint32_t addr) {
    asm volatile("ldmatrix.sync.aligned.m8n8.x4.shared.b16 {%0,%1,%2,%3}, [%4];"
                 : "=r"(r0), "=r"(r1), "=r"(r2), "=r"(r3)
                 : "r"(addr));
}
__device__ __forceinline__ void ldsm4t(uint32_t& r0, uint32_t& r1, uint32_t& r2, uint32_t& r3,
                                       uint32_t addr) {
    asm volatile("ldmatrix.sync.aligned.m8n8.x4.trans.shared.b16 {%0,%1,%2,%3}, [%4];"
                 : "=r"(r0), "=r"(r1), "=r"(r2), "=r"(r3)
                 : "r"(addr));
}
__device__ __forceinline__ void mma_f16(float* c, const uint32_t* a, uint32_t b0, uint32_t b1) {
    asm volatile(
        "mma.sync.aligned.m16n8k16.row.col.f32.f16.f16.f32 "
        "{%0,%1,%2,%3},{%4,%5,%6,%7},{%8,%9},{%0,%1,%2,%3};"
        : "+f"(c[0]), "+f"(c[1]), "+f"(c[2]), "+f"(c[3])
        : "r"(a[0]), "r"(a[1]), "r"(a[2]), "r"(a[3]), "r"(b0), "r"(b1));
}

// swizzled byte offset within a 64-half (128B) row tile
#define ASW(row, colbytes) ((row) * 128 + (((colbytes)) ^ (((row) & 7) << 4)))

// ---------------- fp16 GEMM: C[M,*] = A[M,768] @ Bt[*,768] + bias ----------------
#define BK 64
#define STG_BYTES 32768
#define NSTG 3
#define HG_SMEM (NSTG * STG_BYTES)
#define NKT (DIMC / BK)

template <typename OutT>
__global__ void __launch_bounds__(256, 2) hgemm(
    const __half* __restrict__ A, const __half* __restrict__ Bt,
    const float* __restrict__ bias, OutT* __restrict__ out0,
    OutT* __restrict__ out1, OutT* __restrict__ out2) {
    extern __shared__ char smem[];
    const uint32_t sb = smem_u32(smem);
    const int tid = threadIdx.x;
    const int lane = tid & 31, warp = tid >> 5;
    const int bn = blockIdx.x, bm = blockIdx.y;
    const int wm = (warp & 1) * 64, wn = (warp >> 1) * 32;

    float acc[4][4][4];
#pragma unroll
    for (int i = 0; i < 4; i++)
#pragma unroll
        for (int j = 0; j < 4; j++)
#pragma unroll
            for (int k = 0; k < 4; k++) acc[i][j][k] = 0.f;

    const __half* Ab = A + (size_t)(bm * 128) * DIMC;
    const __half* Bb = Bt + (size_t)(bn * 128) * DIMC;

    auto load_stage = [&](int kt, int s) {
        const uint32_t st = sb + s * STG_BYTES;
#pragma unroll
        for (int i = 0; i < 8; i++) {
            const int c = tid + i * 256;
            if (c < 1024) {
                const int row = c >> 3, ch = c & 7;
                cp16(st + ASW(row, ch * 16), Ab + (size_t)row * DIMC + kt * BK + ch * 8);
            } else {
                const int cb = c - 1024;
                const int row = cb >> 3, ch = cb & 7;
                cp16(st + 16384 + ASW(row, ch * 16), Bb + (size_t)row * DIMC + kt * BK + ch * 8);
            }
        }
        cp_commit();
    };

    load_stage(0, 0);
    load_stage(1, 1);

    for (int kt = 0; kt < NKT; kt++) {
        cp_wait1();
        __syncthreads();
        if (kt + 2 < NKT) load_stage(kt + 2, (kt + 2) % NSTG);
        else cp_commit();

        const uint32_t sA = sb + (kt % NSTG) * STG_BYTES;
        const uint32_t sB = sA + 16384;
        const int l15 = lane & 15, lh = (lane >> 4) * 16;

#pragma unroll
        for (int ks = 0; ks < 4; ks++) {
            const int kb = ks * 32;
            uint32_t af[4][4], bf[2][4];
#pragma unroll
            for (int mt = 0; mt < 4; mt++) {
                const int row = wm + mt * 16 + l15;
                ldsm4(af[mt][0], af[mt][1], af[mt][2], af[mt][3], sA + ASW(row, kb + lh));
            }
#pragma unroll
            for (int bt = 0; bt < 2; bt++) {
                const int row = wn + bt * 16 + l15;
                ldsm4(bf[bt][0], bf[bt][1], bf[bt][2], bf[bt][3], sB + ASW(row, kb + lh));
            }
#pragma unroll
            for (int mt = 0; mt < 4; mt++) {
#pragma unroll
                for (int nt = 0; nt < 4; nt++) {
                    const int bt = nt >> 1, od = nt & 1;
                    mma_f16(acc[mt][nt], af[mt], bf[bt][od], bf[bt][od + 2]);
                }
            }
        }
        __syncthreads();
    }

    const int matsel = (bn * 128) / DIMC;
    OutT* dst = matsel == 0 ? out0 : (matsel == 1 ? out1 : out2);
    const int lcbase = bn * 128 - matsel * DIMC;
#pragma unroll
    for (int mt = 0; mt < 4; mt++) {
#pragma unroll
        for (int nt = 0; nt < 4; nt++) {
            const int row = bm * 128 + wm + mt * 16 + (lane >> 2);
            const int tcol = wn + nt * 8 + (lane & 3) * 2;
            const int gc = bn * 128 + tcol;
            const float b0 = bias[gc], b1 = bias[gc + 1];
            const int lc = lcbase + tcol;
            if (sizeof(OutT) == 4) {
                float2 v0 = make_float2(acc[mt][nt][0] + b0, acc[mt][nt][1] + b1);
                float2 v1 = make_float2(acc[mt][nt][2] + b0, acc[mt][nt][3] + b1);
                *(float2*)&((float*)dst)[(size_t)row * DIMC + lc] = v0;
                *(float2*)&((float*)dst)[(size_t)(row + 8) * DIMC + lc] = v1;
            } else {
                __half2 h0 = __floats2half2_rn(acc[mt][nt][0] + b0, acc[mt][nt][1] + b1);
                __half2 h1 = __floats2half2_rn(acc[mt][nt][2] + b0, acc[mt][nt][3] + b1);
                *(__half2*)&((__half*)dst)[(size_t)row * DIMC + lc] = h0;
                *(__half2*)&((__half*)dst)[(size_t)(row + 8) * DIMC + lc] = h1;
            }
        }
    }
}

// ---------------- pre-passes ----------------
__global__ void cvtx_kernel(const float4* __restrict__ in, uint2* __restrict__ out, int n4) {
    const int i = blockIdx.x * blockDim.x + threadIdx.x;
    if (i >= n4) return;
    const float4 v = in[i];
    __half2 h0 = __floats2half2_rn(v.x, v.y);
    __half2 h1 = __floats2half2_rn(v.z, v.w);
    out[i] = make_uint2(*(uint32_t*)&h0, *(uint32_t*)&h1);
}

__global__ void trwh_kernel(const float* __restrict__ w, __half* __restrict__ dst) {
    __shared__ float t[32][33];
    const int bx = blockIdx.x * 32, by = blockIdx.y * 32;
    const int x = threadIdx.x, y = threadIdx.y;
#pragma unroll
    for (int i = 0; i < 32; i += 8) t[y + i][x] = w[(size_t)(by + y + i) * DIMC + bx + x];
    __syncthreads();
#pragma unroll
    for (int i = 0; i < 32; i += 8)
        dst[(size_t)(bx + y + i) * DIMC + by + x] = __float2half_rn(t[x][y + i]);
}

__global__ void cbias_kernel(const float* __restrict__ qb, const float* __restrict__ vb) {
    const int i = blockIdx.x * blockDim.x + threadIdx.x;
    if (i >= 2304) return;
    const int mat = i / DIMC, c = i - mat * DIMC;
    g_cbias[i] = mat == 0 ? qb[c] : (mat == 2 ? vb[c] : 0.f);
}

// ---------------- CPB MLP + bias gather ----------------
__global__ void cpb_kernel(const float* __restrict__ tabl, const float* __restrict__ w1,
                           const float* __restrict__ b1, const float* __restrict__ w2,
                           const float* __restrict__ b2) {
    __shared__ float red[128 * 12];
    const int r = blockIdx.x;
    const int t = threadIdx.x;
    const float t0 = tabl[r * 3 + 0], t1 = tabl[r * 3 + 1], t2 = tabl[r * 3 + 2];
    float part[12];
#pragma unroll
    for (int hh = 0; hh < 12; hh++) part[hh] = 0.f;
    for (int j = t; j < 512; j += 128) {
        float h = t0 * w1[j] + t1 * w1[512 + j] + t2 * w1[1024 + j] + b1[j];
        h = fmaxf(h, 0.f);
#pragma unroll
        for (int hh = 0; hh < 12; hh++) part[hh] += h * w2[j * 12 + hh];
    }
#pragma unroll
    for (int hh = 0; hh < 12; hh++) red[t * 12 + hh] = part[hh];
    __syncthreads();
    if (t < 12) {
        float s = b2[t];
        for (int i = 0; i < 128; i++) s += red[i * 12 + t];
        g_tbl[r * 12 + t] = s;
    }
}

__global__ void bias_kernel(const int* __restrict__ idx) {
    const int g = blockIdx.x * blockDim.x + threadIdx.x;
    if (g >= 12 * 4096) return;
    const int h = g / 4096, ij = g % 4096;
    const float x = g_tbl[idx[ij] * 12 + h];
    g_bias[g] = 16.f / (1.f + __expf(-x));
}

// ---------------- tensor-core attention per (window, head) ----------------
// smem: q,k,v,p fp16 64x64 swizzled tiles (8KB each) + qn/kn fp32
#define ATTN_SMEM (4 * 8192 + 512)

__global__ void __launch_bounds__(128) attn_kernel(
    const __half* __restrict__ Q, const __half* __restrict__ K,
    const __half* __restrict__ V, const float* __restrict__ LS,
    __half* __restrict__ O) {
    extern __shared__ char sm[];
    const uint32_t sq = smem_u32(sm);
    const uint32_t sk = sq + 8192;
    const uint32_t sv = sk + 8192;
    const uint32_t sp = sv + 8192;
    float* qn = (float*)(sm + 4 * 8192);
    float* kn = qn + 64;

    const int b = blockIdx.x, h = blockIdx.y;
    const int t = threadIdx.x;
    const int lane = t & 31, warp = t >> 5;
    const size_t base = ((size_t)b * NTOK) * DIMC + h * DH;

    // load q,k,v tiles (fp16, swizzled)
#pragma unroll
    for (int i = 0; i < 12; i++) {
        const int idx = t + i * 128;
        const int tens = idx >> 9, rem = idx & 511;
        const int row = rem >> 3, ch = rem & 7;
        const __half* src = (tens == 0 ? Q : (tens == 1 ? K : V)) + base + (size_t)row * DIMC + ch * 8;
        const uint32_t dst = (tens == 0 ? sq : (tens == 1 ? sk : sv)) + ASW(row, ch * 16);
        cp16(dst, src);
    }
    cp_commit();
    cp_wait0();
    __syncthreads();

    // norms (fp32 from fp16)
    {
        const int row = t & 63;
        const uint32_t src = (t < 64 ? sq : sk);
        float s = 0.f;
#pragma unroll
        for (int ch = 0; ch < 8; ch++) {
            uint4 u;
            asm volatile("ld.shared.v4.u32 {%0,%1,%2,%3}, [%4];"
                         : "=r"(u.x), "=r"(u.y), "=r"(u.z), "=r"(u.w)
                         : "r"(src + ASW(row, ch * 16)));
            const uint32_t uu[4] = {u.x, u.y, u.z, u.w};
#pragma unroll
            for (int q2 = 0; q2 < 4; q2++) {
                float2 f = __half22float2(*(const __half2*)&uu[q2]);
                s += f.x * f.x + f.y * f.y;
            }
        }
        if (t < 64) qn[row] = sqrtf(s);
        else kn[row] = sqrtf(s);
    }
    __syncthreads();

    const float scale = fmaxf(LS[h], 0.01f);
    const float* bg = g_bias + h * 4096;
    const int m0 = warp * 16;
    const int l15 = lane & 15, lhb = (lane >> 4) * 16;

    // S = q @ k^T (fp32 accum)
    float acc[8][4];
#pragma unroll
    for (int n = 0; n < 8; n++)
#pragma unroll
        for (int k = 0; k < 4; k++) acc[n][k] = 0.f;
#pragma unroll
    for (int ks = 0; ks < 4; ks++) {
        const int kb = ks * 32;
        uint32_t a[4];
        ldsm4(a[0], a[1], a[2], a[3], sq + ASW(m0 + l15, kb + lhb));
#pragma unroll
        for (int jb = 0; jb < 4; jb++) {
            uint32_t bfr[4];
            ldsm4(bfr[0], bfr[1], bfr[2], bfr[3], sk + ASW(jb * 16 + l15, kb + lhb));
            mma_f16(acc[jb * 2], a, bfr[0], bfr[2]);
            mma_f16(acc[jb * 2 + 1], a, bfr[1], bfr[3]);
        }
    }

    // epilogue: cosine norm + scale + bias
    const int i0 = m0 + (lane >> 2);
    const float iq0 = scale / qn[i0], iq1 = scale / qn[i0 + 8];
    const float qn0 = qn[i0], qn1 = qn[i0 + 8];
#pragma unroll
    for (int nt = 0; nt < 8; nt++) {
        const int c0 = nt * 8 + (lane & 3) * 2;
        const float k0v = kn[c0], k1v = kn[c0 + 1];
        const float d00 = fmaxf(qn0 * k0v, 1e-6f), d01 = fmaxf(qn0 * k1v, 1e-6f);
        const float d10 = fmaxf(qn1 * k0v, 1e-6f), d11 = fmaxf(qn1 * k1v, 1e-6f);
        acc[nt][0] = acc[nt][0] / d00 * scale + bg[i0 * 64 + c0];
        acc[nt][1] = acc[nt][1] / d01 * scale + bg[i0 * 64 + c0 + 1];
        acc[nt][2] = acc[nt][2] / d10 * scale + bg[(i0 + 8) * 64 + c0];
        acc[nt][3] = acc[nt][3] / d11 * scale + bg[(i0 + 8) * 64 + c0 + 1];
    }

    // softmax over each row (cols split across quad lanes)
    float mx0 = -1e30f, mx1 = -1e30f;
#pragma unroll
    for (int nt = 0; nt < 8; nt++) {
        mx0 = fmaxf(mx0, fmaxf(acc[nt][0], acc[nt][1]));
        mx1 = fmaxf(mx1, fmaxf(acc[nt][2], acc[nt][3]));
    }
    mx0 = fmaxf(mx0, __shfl_xor_sync(0xffffffffu, mx0, 1));
    mx0 = fmaxf(mx0, __shfl_xor_sync(0xffffffffu, mx0, 2));
    mx1 = fmaxf(mx1, __shfl_xor_sync(0xffffffffu, mx1, 1));
    mx1 = fmaxf(mx1, __shfl_xor_sync(0xffffffffu, mx1, 2));
    float s0 = 0.f, s1 = 0.f;
#pragma unroll
    for (int nt = 0; nt < 8; nt++) {
        acc[nt][0] = __expf(acc[nt][0] - mx0);
        acc[nt][1] = __expf(acc[nt][1] - mx0);
        acc[nt][2] = __expf(acc[nt][2] - mx1);
        acc[nt][3] = __expf(acc[nt][3] - mx1);
        s0 += acc[nt][0] + acc[nt][1];
        s1 += acc[nt][2] + acc[nt][3];
    }
    s0 += __shfl_xor_sync(0xffffffffu, s0, 1);
    s0 += __shfl_xor_sync(0xffffffffu, s0, 2);
    s1 += __shfl_xor_sync(0xffffffffu, s1, 1);
    s1 += __shfl_xor_sync(0xffffffffu, s1, 2);
    const float inv0 = 1.f / s0, inv1 = 1.f / s1;

    // P (fp16) -> smem, warp-private rows
#pragma unroll
    for (int nt = 0; nt < 8; nt++) {
        const int c0 = nt * 8 + (lane & 3) * 2;
        __half2 h0 = __floats2half2_rn(acc[nt][0] * inv0, acc[nt][1] * inv0);
        __half2 h1 = __floats2half2_rn(acc[nt][2] * inv1, acc[nt][3] * inv1);
        asm volatile("st.shared.b32 [%0], %1;" ::"r"(sp + ASW(i0, c0 * 2)), "r"(*(uint32_t*)&h0));
        asm volatile("st.shared.b32 [%0], %1;" ::"r"(sp + ASW(i0 + 8, c0 * 2)), "r"(*(uint32_t*)&h1));
    }
    __syncwarp();

    // O = P @ V
    float oc[8][4];
#pragma unroll
    for (int n = 0; n < 8; n++)
#pragma unroll
        for (int k = 0; k < 4; k++) oc[n][k] = 0.f;
#pragma unroll
    for (int ks = 0; ks < 4; ks++) {
        const int kb = ks * 32;
        uint32_t a[4];
        ldsm4(a[0], a[1], a[2], a[3], sp + ASW(m0 + l15, kb + lhb));
#pragma unroll
        for (int db = 0; db < 4; db++) {
            uint32_t bfr[4];
            ldsm4t(bfr[0], bfr[1], bfr[2], bfr[3], sv + ASW(ks * 16 + l15, db * 32 + lhb));
            mma_f16(oc[db * 2], a, bfr[0], bfr[1]);
            mma_f16(oc[db * 2 + 1], a, bfr[2], bfr[3]);
        }
    }

    // write ctx (fp16)
#pragma unroll
    for (int nt = 0; nt < 8; nt++) {
        const int d0 = nt * 8 + (lane & 3) * 2;
        __half2 h0 = __floats2half2_rn(oc[nt][0], oc[nt][1]);
        __half2 h1 = __floats2half2_rn(oc[nt][2], oc[nt][3]);
        *(__half2*)&O[base + (size_t)i0 * DIMC + d0] = h0;
        *(__half2*)&O[base + (size_t)(i0 + 8) * DIMC + d0] = h1;
    }
}

// ---------------- launch ----------------
extern "C" void kernel_launch(void* const* d_in, const int* in_sizes, int n_in,
                              void* d_out, int out_size) {
    const float* x   = (const float*)d_in[0];
    const float* q_w = (const float*)d_in[1];
    const float* q_b = (const float*)d_in[2];
    const float* k_w = (const float*)d_in[3];
    const float* v_w = (const float*)d_in[4];
    const float* v_b = (const float*)d_in[5];
    const float* cw1 = (const float*)d_in[6];
    const float* cb1 = (const float*)d_in[7];
    const float* cw2 = (const float*)d_in[8];
    const float* cb2 = (const float*)d_in[9];
    const float* ls  = (const float*)d_in[10];
    const float* pw  = (const float*)d_in[11];
    const float* pb  = (const float*)d_in[12];
    const float* tab = (const float*)d_in[13];
    const int*   idx = (const int*)d_in[14];
    float* out = (float*)d_out;

    const int rows = in_sizes[0] / DIMC;  // 65536
    const int B = rows / NTOK;            // 1024

    __half *dqh, *dkh, *dvh, *dxh, *dch, *dwh, *dwph;
    float* dcb;
    cudaGetSymbolAddress((void**)&dqh, g_qh);
    cudaGetSymbolAddress((void**)&dkh, g_kh);
    cudaGetSymbolAddress((void**)&dvh, g_vh);
    cudaGetSymbolAddress((void**)&dxh, g_xh);
    cudaGetSymbolAddress((void**)&dch, g_ch);
    cudaGetSymbolAddress((void**)&dwh, g_wh);
    cudaGetSymbolAddress((void**)&dwph, g_wph);
    cudaGetSymbolAddress((void**)&dcb, g_cbias);

    cudaFuncSetAttribute(hgemm<__half>, cudaFuncAttributeMaxDynamicSharedMemorySize, HG_SMEM);
    cudaFuncSetAttribute(hgemm<float>, cudaFuncAttributeMaxDynamicSharedMemorySize, HG_SMEM);

    // pre-passes
    const int n4 = rows * DIMC / 4;
    cvtx_kernel<<<(n4 + 255) / 256, 256>>>((const float4*)x, (uint2*)dxh, n4);
    dim3 tb(32, 8), tg(24, 24);
    trwh_kernel<<<tg, tb>>>(q_w, dwh);
    trwh_kernel<<<tg, tb>>>(k_w, dwh + 768 * 768);
    trwh_kernel<<<tg, tb>>>(v_w, dwh + 2 * 768 * 768);
    trwh_kernel<<<tg, tb>>>(pw, dwph);
    cbias_kernel<<<9, 256>>>(q_b, v_b);
    cpb_kernel<<<343, 128>>>(tab, cw1, cb1, cw2, cb2);
    bias_kernel<<<(12 * 4096 + 255) / 256, 256>>>(idx);

    // fused QKV GEMM -> q,k,v (fp16)
    hgemm<__half><<<dim3(2304 / 128, rows / 128), 256, HG_SMEM>>>(dxh, dwh, dcb, dqh, dkh, dvh);

    // tensor-core attention -> ctx (fp16)
    dim3 ga(B, HEADS);
    attn_kernel<<<ga, 128, ATTN_SMEM>>>(dqh, dkh, dvh, ls, dch);

    // proj GEMM -> out (fp32)
    hgemm<float><<<dim3(DIMC / 128, rows / 128), 256, HG_SMEM>>>(dch, dwph, pb, out, out, out);
}